// round 4
// baseline (speedup 1.0000x reference)
#include <cuda_runtime.h>

// Row length (per (b,c) slice) — problem constant: N = 1<<20, B*C = 4 rows.
#define N_ROW   (1 << 20)
#define TABLE_N 1024
#define XMIN    (-10.0f)
#define XSPAN   (20.0f)
#define INV_H   ((float)TABLE_N / XSPAN)
#define HSTEP   (XSPAN / (float)TABLE_N)

// Scratch: tabulated correction f(x) at TABLE_N+1 grid points over [XMIN, XMIN+XSPAN].
__device__ float g_f[TABLE_N + 1];

// ---------------------------------------------------------------------------
// Kernel 1: build the correction table. One warp per table point.
//   lane j owns hidden unit j; layer-2 matvec via shfl broadcast of h1.
// ---------------------------------------------------------------------------
__global__ void build_table_kernel(const float* __restrict__ W1,
                                   const float* __restrict__ b1,
                                   const float* __restrict__ W2,
                                   const float* __restrict__ b2,
                                   const float* __restrict__ W3,
                                   const float* __restrict__ b3) {
    int warp = (blockIdx.x * blockDim.x + threadIdx.x) >> 5;
    int lane = threadIdx.x & 31;
    if (warp > TABLE_N) return;  // whole warp exits together

    float x  = XMIN + (float)warp * HSTEP;
    // layer 1: h1[lane] = tanh(x * W1[lane] + b1[lane])
    float h1 = tanhf(fmaf(__ldg(W1 + lane), x, __ldg(b1 + lane)));
    // layer 2: h2[lane] = tanh(b2[lane] + sum_k h1[k] * W2[k,lane])
    float acc = __ldg(b2 + lane);
#pragma unroll
    for (int k = 0; k < 32; ++k) {
        float hk = __shfl_sync(0xffffffffu, h1, k);
        acc = fmaf(hk, __ldg(W2 + k * 32 + lane), acc);  // coalesced across lanes
    }
    // layer 3: f = b3 + sum_j tanh(h2[j]) * W3[j]  (warp reduction)
    float p = tanhf(acc) * __ldg(W3 + lane);
#pragma unroll
    for (int off = 16; off > 0; off >>= 1)
        p += __shfl_xor_sync(0xffffffffu, p, off);
    if (lane == 0) g_f[warp] = p + __ldg(b3);
}

// ---------------------------------------------------------------------------
// Kernel 2: fused Laplacian + table-lerp correction. float4 per thread,
// grid-stride. Table in shared as float2 pairs -> one LDS.64 per lookup.
// ---------------------------------------------------------------------------
__global__ __launch_bounds__(256) void lap_corr_kernel(const float* __restrict__ u,
                                                       float* __restrict__ out,
                                                       int total) {
    __shared__ float2 tab[TABLE_N];
    for (int k = threadIdx.x; k < TABLE_N; k += blockDim.x)
        tab[k] = make_float2(g_f[k], g_f[k + 1]);
    __syncthreads();

    const int nv = total >> 2;  // float4 units
    for (int v = blockIdx.x * blockDim.x + threadIdx.x; v < nv;
         v += gridDim.x * blockDim.x) {
        const int i   = v << 2;
        const int pos = i & (N_ROW - 1);

        const float4 c = *reinterpret_cast<const float4*>(u + i);
        const float left  = (pos == 0)           ? 0.0f : __ldg(u + i - 1);
        const float right = (pos == N_ROW - 4)   ? 0.0f : __ldg(u + i + 4);

        float4 r;
        r.x = fmaf(-2.0f, c.x, left + c.y);
        r.y = fmaf(-2.0f, c.y, c.x + c.z);
        r.z = fmaf(-2.0f, c.z, c.y + c.w);
        r.w = fmaf(-2.0f, c.w, c.z + right);

#define CORR_ADD(val, dst)                                           \
        {                                                            \
            float t = ((val) - XMIN) * INV_H;                        \
            t = fminf(fmaxf(t, 0.0f), (float)TABLE_N - 0.001f);      \
            int   ki = (int)t;                                       \
            float fr = t - (float)ki;                                \
            float2 e = tab[ki];                                      \
            (dst) += fmaf(e.y - e.x, fr, e.x);                       \
        }
        CORR_ADD(c.x, r.x)
        CORR_ADD(c.y, r.y)
        CORR_ADD(c.z, r.z)
        CORR_ADD(c.w, r.w)
#undef CORR_ADD

        *reinterpret_cast<float4*>(out + i) = r;
    }
}

// ---------------------------------------------------------------------------
// Launch
// ---------------------------------------------------------------------------
extern "C" void kernel_launch(void* const* d_in, const int* in_sizes, int n_in,
                              void* d_out, int out_size) {
    const float* u  = (const float*)d_in[0];
    const float* W1 = (const float*)d_in[1];
    const float* b1 = (const float*)d_in[2];
    const float* W2 = (const float*)d_in[3];
    const float* b2 = (const float*)d_in[4];
    const float* W3 = (const float*)d_in[5];
    const float* b3 = (const float*)d_in[6];
    float* out = (float*)d_out;
    const int total = in_sizes[0];  // 4 * 1048576

    // 1025 table points, one warp each, 8 warps/block -> 129 blocks
    build_table_kernel<<<(TABLE_N + 1 + 7) / 8, 256>>>(W1, b1, W2, b2, W3, b3);

    const int nv = total >> 2;
    int blocks = (nv + 255) / 256;
    if (blocks > 1184) blocks = 1184;  // ~8 CTAs/SM, keeps table-fill L2 traffic small
    lap_corr_kernel<<<blocks, 256>>>(u, out, total);
}